// round 4
// baseline (speedup 1.0000x reference)
#include <cuda_runtime.h>
#include <cuda_fp16.h>
#include <cstdint>

#define D_DIM    256
#define ROWS     32768
#define TILE_M   64
#define NC       32
#define THREADS  256

// fp16 label tables (converted by prepass): intent [512*256], slot [1024*256]
__device__ __half Wh[(512 + 1024) * 256];

// smem byte offsets
#define XS   0               // X tile: 64 rows * 512B (fp16, swizzled); dead after prologue
#define WS   32768           // 2 x 16384 W chunk double buffer
#define PS   65536           // P: 64 rows * 80B (padded)
#define DEN  70656           // 3 * 64 floats (wh0, wh1, inv)
#define SMEM_BYTES 71424

static __device__ __forceinline__ uint32_t smem_u32(const void* p) {
    uint32_t a;
    asm("{ .reg .u64 t; cvta.to.shared.u64 t, %1; cvt.u32.u64 %0, t; }" : "=r"(a) : "l"(p));
    return a;
}
static __device__ __forceinline__ uint32_t pack2(float lo, float hi) {
    __half2 h = __floats2half2_rn(lo, hi);
    return reinterpret_cast<uint32_t&>(h);
}

#define LDSM_X4(r0, r1, r2, r3, p) \
    asm volatile("ldmatrix.sync.aligned.m8n8.x4.shared.b16 {%0,%1,%2,%3}, [%4];" \
        : "=r"(r0), "=r"(r1), "=r"(r2), "=r"(r3) : "r"(p))
#define LDSM_X4T(r0, r1, r2, r3, p) \
    asm volatile("ldmatrix.sync.aligned.m8n8.x4.trans.shared.b16 {%0,%1,%2,%3}, [%4];" \
        : "=r"(r0), "=r"(r1), "=r"(r2), "=r"(r3) : "r"(p))
#define MMA(C, a0, a1, a2, a3, b0, b1) \
    asm volatile("mma.sync.aligned.m16n8k16.row.col.f32.f16.f16.f32 " \
        "{%0,%1,%2,%3}, {%4,%5,%6,%7}, {%8,%9}, {%0,%1,%2,%3};" \
        : "+f"((C)[0]), "+f"((C)[1]), "+f"((C)[2]), "+f"((C)[3]) \
        : "r"(a0), "r"(a1), "r"(a2), "r"(a3), "r"(b0), "r"(b1))
#define CP16(dst, src) \
    asm volatile("cp.async.cg.shared.global [%0], [%1], 16;" :: "r"(dst), "l"(src))
#define CP_COMMIT() asm volatile("cp.async.commit_group;" ::: "memory")
#define CP_WAIT1() asm volatile("cp.async.wait_group 1;" ::: "memory")
#define CP_WAIT0() asm volatile("cp.async.wait_group 0;" ::: "memory")

// ---- prepass: convert fp32 W tables to fp16 global
__global__ void wcvt_kernel(const float* __restrict__ wi, const float* __restrict__ ws) {
    int i = blockIdx.x * blockDim.x + threadIdx.x;   // one float4 each
    __half2* dst = (__half2*)Wh;
    if (i < 32768) {                                  // intent: 512*256/4
        float4 v = __ldg((const float4*)wi + i);
        dst[i * 2]     = __floats2half2_rn(v.x, v.y);
        dst[i * 2 + 1] = __floats2half2_rn(v.z, v.w);
    }
    if (i < 65536) {                                  // slot: 1024*256/4
        float4 v = __ldg((const float4*)ws + i);
        __half2* d2 = (__half2*)(Wh + 512 * 256);
        d2[i * 2]     = __floats2half2_rn(v.x, v.y);
        d2[i * 2 + 1] = __floats2half2_rn(v.z, v.w);
    }
}

__global__ void __launch_bounds__(THREADS, 1)
label_attn_fp16(const float* __restrict__ x_intent,
                const float* __restrict__ x_slot,
                float* __restrict__ out)
{
    extern __shared__ char smem[];
    const uint32_t sb = smem_u32(smem);
    const int tid = threadIdx.x, lane = tid & 31, warp = tid >> 5;
    const int wm = warp >> 1, wh = warp & 1;   // GEMM1 roles
    const int nw = warp;                       // GEMM2 role: n32 column slice

    int bid = blockIdx.x, branch, tile;
    if (bid < 512) { branch = 1; tile = bid; } else { branch = 0; tile = bid - 512; }
    const float* __restrict__ Xin = branch ? x_slot : x_intent;
    const __half* __restrict__ Wg = Wh + (branch ? 512 * 256 : 0);
    float* __restrict__ Oout = out + (size_t)branch * ROWS * D_DIM;
    const int nch = branch ? 32 : 16;
    const long row0 = (long)tile * TILE_M;

    // ---- X tile: fp32 gmem -> fp16 swizzled smem (once; staging only)
    {
        const float4* X4 = (const float4*)(Xin + row0 * D_DIM);
        for (int i = tid; i < TILE_M * 64; i += THREADS) {
            int r = i >> 6, c4 = i & 63;
            float4 v = __ldg(&X4[r * 64 + c4]);
            uint32_t h0 = pack2(v.x, v.y), h1 = pack2(v.z, v.w);
            int ck = c4 >> 1;
            uint32_t dst = sb + XS + r * 512 + ((ck ^ (r & 7)) << 4) + ((c4 & 1) << 3);
            asm volatile("st.shared.v2.b32 [%0], {%1, %2};" :: "r"(dst), "r"(h0), "r"(h1) : "memory");
        }
    }

    // ---- W chunk cp.async loader
    auto issue_w = [&](int chunk, int b) {
        const __half* src0 = Wg + (size_t)chunk * NC * 256;
        for (int i = tid; i < 1024; i += THREADS) {
            int r = i >> 5, c = i & 31;
            uint32_t dst = sb + WS + (b << 14) + r * 512 + ((c ^ (r & 7)) << 4);
            CP16(dst, src0 + r * 256 + c * 8);
        }
        CP_COMMIT();
    };
    issue_w(0, 0);
    issue_w(1, 1);

    // ---- per-thread addressing
    const int lo7 = lane & 7, hi = lane >> 4, g8 = ((lane >> 3) & 1) << 3;
    const int gg = lane >> 2, tt = lane & 3;
    const uint32_t xa_row = sb + XS + (wm * 16 + lo7 + g8) * 512;
    const int xa_sw = (wm * 16 + lo7 + g8) & 7;
    const uint32_t wb_row = (wh * 16 + lo7 + g8) * 512;      // GEMM1 B rows = labels
    const int wb_sw = (wh * 16 + lo7 + g8) & 7;
    const uint32_t pa_base = sb + PS + (lo7 + g8) * 80;      // GEMM2 A: + mt*16*80
    const uint32_t b2_row = (lo7 + g8) * 512;                // GEMM2 B rows = labels (k)
    const int b2_sw = lo7;
    const uint32_t ps_st = sb + PS + (wm * 16 + gg) * 80 + (wh * 16 + 2 * tt) * 2;

    __syncthreads();

    // ---- X A-fragments: load ONCE into registers (loop-invariant)
    uint32_t xf[64];
#pragma unroll
    for (int kk = 0; kk < 16; kk++)
        LDSM_X4(xf[4 * kk], xf[4 * kk + 1], xf[4 * kk + 2], xf[4 * kk + 3],
                xa_row + (((2 * kk + hi) ^ xa_sw) << 4));

    float Oa[64];
#pragma unroll
    for (int j = 0; j < 64; j++) Oa[j] = 0.0f;
    float den0 = 0.0f, den1 = 0.0f;

    for (int i = 0; i < nch; i++) {
        const uint32_t Wbase = sb + WS + ((i & 1) << 14);
        if (i == nch - 1) CP_WAIT0(); else CP_WAIT1();
        __syncthreads();   // W buf i ready everywhere; P from chunk i-1 consumed

        // ---- GEMM1: S[m16 x n16] = X(regs) * Wchunk^T; B ldsm double-buffered
        float S[8];
#pragma unroll
        for (int j = 0; j < 8; j++) S[j] = 0.0f;
        {
            uint32_t b[2][4];
            LDSM_X4(b[0][0], b[0][1], b[0][2], b[0][3],
                    Wbase + wb_row + ((hi ^ wb_sw) << 4));
#pragma unroll
            for (int kk = 0; kk < 16; kk++) {
                int cur = kk & 1;
                if (kk < 15)
                    LDSM_X4(b[cur ^ 1][0], b[cur ^ 1][1], b[cur ^ 1][2], b[cur ^ 1][3],
                            Wbase + wb_row + (((2 * (kk + 1) + hi) ^ wb_sw) << 4));
                MMA(S,     xf[4 * kk], xf[4 * kk + 1], xf[4 * kk + 2], xf[4 * kk + 3],
                    b[cur][0], b[cur][2]);
                MMA(S + 4, xf[4 * kk], xf[4 * kk + 1], xf[4 * kk + 2], xf[4 * kk + 3],
                    b[cur][1], b[cur][3]);
            }
        }

        // ---- exp, row-denominator partials, stage P (fp16)
        float e0 = __expf(S[0]), e1 = __expf(S[1]), e2 = __expf(S[2]), e3 = __expf(S[3]);
        float e4 = __expf(S[4]), e5 = __expf(S[5]), e6 = __expf(S[6]), e7 = __expf(S[7]);
        den0 += e0 + e1 + e4 + e5;
        den1 += e2 + e3 + e6 + e7;
        {
            uint32_t p0 = pack2(e0, e1), p1 = pack2(e2, e3);
            uint32_t p2 = pack2(e4, e5), p3 = pack2(e6, e7);
            asm volatile("st.shared.b32 [%0], %1;" :: "r"(ps_st),       "r"(p0) : "memory");
            asm volatile("st.shared.b32 [%0], %1;" :: "r"(ps_st + 640), "r"(p1) : "memory");
            asm volatile("st.shared.b32 [%0], %1;" :: "r"(ps_st + 16),  "r"(p2) : "memory");
            asm volatile("st.shared.b32 [%0], %1;" :: "r"(ps_st + 656), "r"(p3) : "memory");
        }
        __syncthreads();   // P visible

        // ---- GEMM2: warp owns cols [nw*32, nw*32+32), all 64 rows
        //      O[m64 x n32] += P[m64 x 32] * Wchunk[32 x n32]
#pragma unroll
        for (int ks = 0; ks < 2; ks++) {
            uint32_t a[4][4];
#pragma unroll
            for (int mt = 0; mt < 4; mt++)
                LDSM_X4(a[mt][0], a[mt][1], a[mt][2], a[mt][3],
                        pa_base + mt * 1280 + ((2 * ks + hi) << 4));
#pragma unroll
            for (int nt = 0; nt < 2; nt++) {
                uint32_t r0, r1, r2, r3;
                int nc_ = nw * 4 + 2 * nt + hi;
                LDSM_X4T(r0, r1, r2, r3,
                         Wbase + (ks << 13) + b2_row + ((nc_ ^ b2_sw) << 4));
#pragma unroll
                for (int mt = 0; mt < 4; mt++) {
                    MMA(Oa + (mt * 4 + nt * 2) * 4,     a[mt][0], a[mt][1], a[mt][2], a[mt][3], r0, r1);
                    MMA(Oa + (mt * 4 + nt * 2 + 1) * 4, a[mt][0], a[mt][1], a[mt][2], a[mt][3], r2, r3);
                }
            }
        }
        __syncthreads();   // W buf (i&1) free, P consumed

        if (i + 2 < nch) issue_w(i + 2, i & 1);
    }

    // ---- denominators: quad reduce, cross-half sum, invert
    den0 += __shfl_xor_sync(0xffffffff, den0, 1);
    den0 += __shfl_xor_sync(0xffffffff, den0, 2);
    den1 += __shfl_xor_sync(0xffffffff, den1, 1);
    den1 += __shfl_xor_sync(0xffffffff, den1, 2);
    float* dsm = (float*)(smem + DEN);
    if (tt == 0) {
        dsm[wh * 64 + wm * 16 + gg]     = den0;
        dsm[wh * 64 + wm * 16 + gg + 8] = den1;
    }
    __syncthreads();
    if (tid < 64) dsm[128 + tid] = 1.0f / (dsm[tid] + dsm[64 + tid]);
    __syncthreads();

    // ---- scaled store: warp nw covers rows 0..63, cols nw*32..+31
#pragma unroll
    for (int mt = 0; mt < 4; mt++) {
        const float ia = dsm[128 + mt * 16 + gg];
        const float ib = dsm[128 + mt * 16 + gg + 8];
        const long r_a = row0 + mt * 16 + gg, r_b = r_a + 8;
#pragma unroll
        for (int t4 = 0; t4 < 4; t4++) {
            int c = nw * 32 + t4 * 8 + 2 * tt;
            int idx = (mt * 4 + t4) * 4;
            *(float2*)&Oout[r_a * 256 + c] = make_float2(Oa[idx]     * ia, Oa[idx + 1] * ia);
            *(float2*)&Oout[r_b * 256 + c] = make_float2(Oa[idx + 2] * ib, Oa[idx + 3] * ib);
        }
    }
}

extern "C" void kernel_launch(void* const* d_in, const int* in_sizes, int n_in,
                              void* d_out, int out_size)
{
    const float* x_intent = (const float*)d_in[0];
    const float* x_slot   = (const float*)d_in[1];
    // d_in[2] = mask (unused)
    const float* w_intent = (const float*)d_in[3];
    const float* w_slot   = (const float*)d_in[4];
    float* out = (float*)d_out;

    wcvt_kernel<<<256, 256>>>(w_intent, w_slot);

    cudaFuncSetAttribute(label_attn_fp16,
                         cudaFuncAttributeMaxDynamicSharedMemorySize, SMEM_BYTES);
    label_attn_fp16<<<1024, THREADS, SMEM_BYTES>>>(x_intent, x_slot, out);
}

// round 5
// speedup vs baseline: 1.0966x; 1.0966x over previous
#include <cuda_runtime.h>
#include <cuda_fp16.h>
#include <cstdint>

#define D_DIM    256
#define ROWS     32768
#define TILE_M   64
#define NC       32
#define THREADS  256

// fp16 label tables (converted by prepass): intent [512*256], slot [1024*256]
__device__ __half Wh[(512 + 1024) * 256];

// smem byte offsets
#define XS   0               // X tile: 64 rows * 512B (fp16, swizzled)
#define WS   32768           // 3 x 16384 W chunk triple buffer
#define PS   81920           // P: 64 rows * 80B (padded)
#define DEN  87040           // 3 * 64 floats
#define SMEM_BYTES 87808

static __device__ __forceinline__ uint32_t smem_u32(const void* p) {
    uint32_t a;
    asm("{ .reg .u64 t; cvta.to.shared.u64 t, %1; cvt.u32.u64 %0, t; }" : "=r"(a) : "l"(p));
    return a;
}
static __device__ __forceinline__ uint32_t pack2(float lo, float hi) {
    __half2 h = __floats2half2_rn(lo, hi);
    return reinterpret_cast<uint32_t&>(h);
}

#define LDSM_X4(r0, r1, r2, r3, p) \
    asm volatile("ldmatrix.sync.aligned.m8n8.x4.shared.b16 {%0,%1,%2,%3}, [%4];" \
        : "=r"(r0), "=r"(r1), "=r"(r2), "=r"(r3) : "r"(p))
#define LDSM_X4T(r0, r1, r2, r3, p) \
    asm volatile("ldmatrix.sync.aligned.m8n8.x4.trans.shared.b16 {%0,%1,%2,%3}, [%4];" \
        : "=r"(r0), "=r"(r1), "=r"(r2), "=r"(r3) : "r"(p))
#define MMA(C, a0, a1, a2, a3, b0, b1) \
    asm volatile("mma.sync.aligned.m16n8k16.row.col.f32.f16.f16.f32 " \
        "{%0,%1,%2,%3}, {%4,%5,%6,%7}, {%8,%9}, {%0,%1,%2,%3};" \
        : "+f"((C)[0]), "+f"((C)[1]), "+f"((C)[2]), "+f"((C)[3]) \
        : "r"(a0), "r"(a1), "r"(a2), "r"(a3), "r"(b0), "r"(b1))
#define CP16(dst, src) \
    asm volatile("cp.async.cg.shared.global [%0], [%1], 16;" :: "r"(dst), "l"(src))
#define CP_COMMIT() asm volatile("cp.async.commit_group;" ::: "memory")
#define CP_WAIT1() asm volatile("cp.async.wait_group 1;" ::: "memory")

// ---- prepass: convert fp32 W tables to fp16 global
__global__ void wcvt_kernel(const float* __restrict__ wi, const float* __restrict__ ws) {
    int i = blockIdx.x * blockDim.x + threadIdx.x;
    __half2* dst = (__half2*)Wh;
    if (i < 32768) {
        float4 v = __ldg((const float4*)wi + i);
        dst[i * 2]     = __floats2half2_rn(v.x, v.y);
        dst[i * 2 + 1] = __floats2half2_rn(v.z, v.w);
    }
    if (i < 65536) {
        float4 v = __ldg((const float4*)ws + i);
        __half2* d2 = (__half2*)(Wh + 512 * 256);
        d2[i * 2]     = __floats2half2_rn(v.x, v.y);
        d2[i * 2 + 1] = __floats2half2_rn(v.z, v.w);
    }
}

__global__ void __launch_bounds__(THREADS, 2)
label_attn_fp16(const float* __restrict__ x_intent,
                const float* __restrict__ x_slot,
                float* __restrict__ out)
{
    extern __shared__ char smem[];
    const uint32_t sb = smem_u32(smem);
    const int tid = threadIdx.x, lane = tid & 31, warp = tid >> 5;
    const int wm = warp >> 1, wh = warp & 1;   // GEMM1 roles
    const int nw = warp;                       // GEMM2 role: n32 column slice

    int bid = blockIdx.x, branch, tile;
    if (bid < 512) { branch = 1; tile = bid; } else { branch = 0; tile = bid - 512; }
    const float* __restrict__ Xin = branch ? x_slot : x_intent;
    const __half* __restrict__ Wg = Wh + (branch ? 512 * 256 : 0);
    float* __restrict__ Oout = out + (size_t)branch * ROWS * D_DIM;
    const int nch = branch ? 32 : 16;
    const long row0 = (long)tile * TILE_M;

    // ---- X tile: fp32 gmem -> fp16 swizzled smem (once)
    {
        const float4* X4 = (const float4*)(Xin + row0 * D_DIM);
        for (int i = tid; i < TILE_M * 64; i += THREADS) {
            int r = i >> 6, c4 = i & 63;
            float4 v = __ldg(&X4[r * 64 + c4]);
            uint32_t h0 = pack2(v.x, v.y), h1 = pack2(v.z, v.w);
            int ck = c4 >> 1;
            uint32_t dst = sb + XS + r * 512 + ((ck ^ (r & 7)) << 4) + ((c4 & 1) << 3);
            asm volatile("st.shared.v2.b32 [%0], {%1, %2};" :: "r"(dst), "r"(h0), "r"(h1) : "memory");
        }
    }

    // ---- W chunk cp.async loader (buffer b in {0,1,2})
    auto issue_w = [&](int chunk, int b) {
        const __half* src0 = Wg + (size_t)chunk * NC * 256;
        for (int i = tid; i < 1024; i += THREADS) {
            int r = i >> 5, c = i & 31;
            uint32_t dst = sb + WS + b * 16384 + r * 512 + ((c ^ (r & 7)) << 4);
            CP16(dst, src0 + r * 256 + c * 8);
        }
        CP_COMMIT();
    };
    issue_w(0, 0);
    issue_w(1, 1);

    // ---- per-thread addressing
    const int lo7 = lane & 7, hi = lane >> 4, g8 = ((lane >> 3) & 1) << 3;
    const int gg = lane >> 2, tt = lane & 3;
    const uint32_t xa_row = sb + XS + (wm * 16 + lo7 + g8) * 512;
    const int xa_sw = (wm * 16 + lo7 + g8) & 7;
    const uint32_t wb_row = (wh * 16 + lo7 + g8) * 512;      // GEMM1 B rows = labels
    const int wb_sw = (wh * 16 + lo7 + g8) & 7;
    const uint32_t pa_base = sb + PS + (lo7 + g8) * 80;      // GEMM2 A: + mt*16*80
    const uint32_t b2_row = (lo7 + g8) * 512;                // GEMM2 B rows = labels (k)
    const int b2_sw = lo7;
    const uint32_t ps_st = sb + PS + (wm * 16 + gg) * 80 + (wh * 16 + 2 * tt) * 2;

    float Oa[64];
#pragma unroll
    for (int j = 0; j < 64; j++) Oa[j] = 0.0f;
    float den0 = 0.0f, den1 = 0.0f;

    int wbuf = 0;   // = i % 3
    for (int i = 0; i < nch; i++) {
        const uint32_t Wbase = sb + WS + wbuf * 16384;
        CP_WAIT1();        // one commit per chunk => group i complete
        __syncthreads();   // sync(a): W buf visible; P(i-1) consumed; buf (i+2)%3 safe to fill later

        // ---- GEMM1: S[m16 x n16] = X * Wchunk^T; B ldsm double-buffered in regs
        float S[8];
#pragma unroll
        for (int j = 0; j < 8; j++) S[j] = 0.0f;
        {
            uint32_t b[2][4];
            LDSM_X4(b[0][0], b[0][1], b[0][2], b[0][3],
                    Wbase + wb_row + ((hi ^ wb_sw) << 4));
#pragma unroll
            for (int kk = 0; kk < 16; kk++) {
                int cur = kk & 1;
                uint32_t a0, a1, a2, a3;
                LDSM_X4(a0, a1, a2, a3, xa_row + (((2 * kk + hi) ^ xa_sw) << 4));
                if (kk < 15)
                    LDSM_X4(b[cur ^ 1][0], b[cur ^ 1][1], b[cur ^ 1][2], b[cur ^ 1][3],
                            Wbase + wb_row + (((2 * (kk + 1) + hi) ^ wb_sw) << 4));
                MMA(S,     a0, a1, a2, a3, b[cur][0], b[cur][2]);
                MMA(S + 4, a0, a1, a2, a3, b[cur][1], b[cur][3]);
            }
        }

        // ---- exp, row-denominator partials, stage P (fp16)
        float e0 = __expf(S[0]), e1 = __expf(S[1]), e2 = __expf(S[2]), e3 = __expf(S[3]);
        float e4 = __expf(S[4]), e5 = __expf(S[5]), e6 = __expf(S[6]), e7 = __expf(S[7]);
        den0 += e0 + e1 + e4 + e5;
        den1 += e2 + e3 + e6 + e7;
        {
            uint32_t p0 = pack2(e0, e1), p1 = pack2(e2, e3);
            uint32_t p2 = pack2(e4, e5), p3 = pack2(e6, e7);
            asm volatile("st.shared.b32 [%0], %1;" :: "r"(ps_st),       "r"(p0) : "memory");
            asm volatile("st.shared.b32 [%0], %1;" :: "r"(ps_st + 640), "r"(p1) : "memory");
            asm volatile("st.shared.b32 [%0], %1;" :: "r"(ps_st + 16),  "r"(p2) : "memory");
            asm volatile("st.shared.b32 [%0], %1;" :: "r"(ps_st + 656), "r"(p3) : "memory");
        }
        __syncthreads();   // sync(b): P visible

        // ---- GEMM2: warp owns cols [nw*32, nw*32+32), all 64 rows
#pragma unroll
        for (int ks = 0; ks < 2; ks++) {
            uint32_t a[4][4];
#pragma unroll
            for (int mt = 0; mt < 4; mt++)
                LDSM_X4(a[mt][0], a[mt][1], a[mt][2], a[mt][3],
                        pa_base + mt * 1280 + ((2 * ks + hi) << 4));
#pragma unroll
            for (int nt = 0; nt < 2; nt++) {
                uint32_t r0, r1, r2, r3;
                int nc_ = nw * 4 + 2 * nt + hi;
                LDSM_X4T(r0, r1, r2, r3,
                         Wbase + (ks << 13) + b2_row + ((nc_ ^ b2_sw) << 4));
#pragma unroll
                for (int mt = 0; mt < 4; mt++) {
                    MMA(Oa + (mt * 4 + nt * 2) * 4,     a[mt][0], a[mt][1], a[mt][2], a[mt][3], r0, r1);
                    MMA(Oa + (mt * 4 + nt * 2 + 1) * 4, a[mt][0], a[mt][1], a[mt][2], a[mt][3], r2, r3);
                }
            }
        }

        // ---- prefetch W chunk i+2 into buf (i+2)%3 (safe: its last readers
        //      finished chunk i-1 before sync(a) of this chunk). One commit/chunk.
        int nb = wbuf + 2; if (nb >= 3) nb -= 3;
        if (i + 2 < nch) issue_w(i + 2, nb); else CP_COMMIT();
        if (++wbuf == 3) wbuf = 0;
    }

    // ---- denominators: quad reduce, cross-half sum, invert
    den0 += __shfl_xor_sync(0xffffffff, den0, 1);
    den0 += __shfl_xor_sync(0xffffffff, den0, 2);
    den1 += __shfl_xor_sync(0xffffffff, den1, 1);
    den1 += __shfl_xor_sync(0xffffffff, den1, 2);
    float* dsm = (float*)(smem + DEN);
    if (tt == 0) {
        dsm[wh * 64 + wm * 16 + gg]     = den0;
        dsm[wh * 64 + wm * 16 + gg + 8] = den1;
    }
    __syncthreads();
    if (tid < 64) dsm[128 + tid] = 1.0f / (dsm[tid] + dsm[64 + tid]);
    __syncthreads();

    // ---- scaled store: warp nw covers rows 0..63, cols nw*32..+31
#pragma unroll
    for (int mt = 0; mt < 4; mt++) {
        const float ia = dsm[128 + mt * 16 + gg];
        const float ib = dsm[128 + mt * 16 + gg + 8];
        const long r_a = row0 + mt * 16 + gg, r_b = r_a + 8;
#pragma unroll
        for (int t4 = 0; t4 < 4; t4++) {
            int c = nw * 32 + t4 * 8 + 2 * tt;
            int idx = (mt * 4 + t4) * 4;
            *(float2*)&Oout[r_a * 256 + c] = make_float2(Oa[idx]     * ia, Oa[idx + 1] * ia);
            *(float2*)&Oout[r_b * 256 + c] = make_float2(Oa[idx + 2] * ib, Oa[idx + 3] * ib);
        }
    }
}

extern "C" void kernel_launch(void* const* d_in, const int* in_sizes, int n_in,
                              void* d_out, int out_size)
{
    const float* x_intent = (const float*)d_in[0];
    const float* x_slot   = (const float*)d_in[1];
    // d_in[2] = mask (unused)
    const float* w_intent = (const float*)d_in[3];
    const float* w_slot   = (const float*)d_in[4];
    float* out = (float*)d_out;

    wcvt_kernel<<<256, 256>>>(w_intent, w_slot);

    cudaFuncSetAttribute(label_attn_fp16,
                         cudaFuncAttributeMaxDynamicSharedMemorySize, SMEM_BYTES);
    label_attn_fp16<<<1024, THREADS, SMEM_BYTES>>>(x_intent, x_slot, out);
}